// round 1
// baseline (speedup 1.0000x reference)
#include <cuda_runtime.h>

#define NN 1024
#define NB 32
#define H 0.061f
#define EPSF 1e-8f

__device__ double g_acc[2];   // [0] = sum(zc * curvature_relu), [1] = sum(zc)

__global__ void curv_init_kernel() {
    g_acc[0] = 0.0;
    g_acc[1] = 0.0;
}

__global__ void __launch_bounds__(256) curv_main_kernel(const float* __restrict__ phi) {
    const int b = blockIdx.z;
    const float* __restrict__ p = phi + (size_t)b * NN * NN;

    const float inv2h  = 0.5f / H;            // 1/(2h)
    const float inv4h2 = 0.25f / (H * H);     // 1/(4h^2)
    const float invth  = 1.0f / (1.0f + EPSF);// 1/(CURV_THRESH+eps)

    double ln = 0.0;  // local sum of zc*curvature_relu
    double lz = 0.0;  // local sum of zc

    for (int y = 1 + blockIdx.y * blockDim.y + threadIdx.y; y <= NN - 2;
         y += gridDim.y * blockDim.y) {
        const int row = y * NN;
        for (int x = 1 + blockIdx.x * blockDim.x + threadIdx.x; x <= NN - 2;
             x += gridDim.x * blockDim.x) {
            const int i = row + x;
            float c  = p[i];
            float e  = p[i + 1];
            float w  = p[i - 1];
            float s  = p[i + NN];
            float n  = p[i - NN];
            float se = p[i + NN + 1];
            float sw = p[i + NN - 1];
            float ne = p[i - NN + 1];
            float nw = p[i - NN - 1];

            float ddx = (e - w) * inv2h;
            float ddy = (s - n) * inv2h;
            float dxy = (se - sw - ne + nw) * inv4h2;

            float d   = ddx * ddx + ddy * ddy;
            float den = d * sqrtf(d);                         // (ddx^2+ddy^2)^1.5
            float num = dxy * ddy * ddy - 2.0f * ddy * ddx * dxy + dxy * ddx * ddx;
            float curv = num / (den + EPSF);

            float t  = curv * invth;
            float cr = t * t - 1.0f;
            cr = cr > 0.0f ? cr : 0.0f;                       // relu

            bool zc = (c * e < 0.0f) | (c * w < 0.0f) |
                      (c * s < 0.0f) | (c * n < 0.0f);
            if (zc) {
                ln += (double)cr;
                lz += 1.0;
            }
        }
    }

    // warp reduction (block is (32,8): threadIdx.y == warp id, threadIdx.x == lane)
    #pragma unroll
    for (int o = 16; o > 0; o >>= 1) {
        ln += __shfl_down_sync(0xffffffffu, ln, o);
        lz += __shfl_down_sync(0xffffffffu, lz, o);
    }

    __shared__ double sn[8];
    __shared__ double sz[8];
    if (threadIdx.x == 0) {
        sn[threadIdx.y] = ln;
        sz[threadIdx.y] = lz;
    }
    __syncthreads();

    if (threadIdx.x == 0 && threadIdx.y == 0) {
        double an = 0.0, az = 0.0;
        #pragma unroll
        for (int k = 0; k < 8; k++) { an += sn[k]; az += sz[k]; }
        atomicAdd(&g_acc[0], an);
        atomicAdd(&g_acc[1], az);
    }
}

__global__ void curv_final_kernel(float* __restrict__ out) {
    out[0] = (float)(g_acc[0] / (g_acc[1] + 1e-8));
}

extern "C" void kernel_launch(void* const* d_in, const int* in_sizes, int n_in,
                              void* d_out, int out_size) {
    const float* phi = (const float*)d_in[0];
    float* out = (float*)d_out;

    curv_init_kernel<<<1, 1>>>();

    dim3 block(32, 8, 1);
    dim3 grid(4, 32, NB);   // 4096 blocks: x-stride 128, y-stride 256, z = batch
    curv_main_kernel<<<grid, block>>>(phi);

    curv_final_kernel<<<1, 1>>>(out);
}

// round 5
// speedup vs baseline: 2.9593x; 2.9593x over previous
#include <cuda_runtime.h>

#define NN 1024
#define NB 32
#define RSTRIP 8
#define NSTRIPS 128          // 1022 rows / 8, last strip short (6 rows)
#define GY 32
#define TOTAL_BLOCKS (GY * NB)

// den = 2h * d * sqrt(d) + 16 h^4 * eps   (exact rescale of ((d/4h^2)^1.5 + eps))
#define C1 0.122f            // 2h, h = 0.061
#define C2 2.2153277e-12f    // 16 * h^4 * 1e-8

__device__ double g_acc[2];          // [0] = sum(zc*cr), [1] = sum(zc)
__device__ unsigned int g_done;

__device__ __forceinline__ void load_row6(const float* __restrict__ rp, int g,
                                          int lane, int chunk, float r[6]) {
    float4 v = *reinterpret_cast<const float4*>(rp + 4 * g);
    float lf = __shfl_up_sync(0xffffffffu, v.w, 1);
    float rt = __shfl_down_sync(0xffffffffu, v.x, 1);
    if (lane == 0)  lf = (chunk > 0) ? rp[4 * g - 1] : 0.0f;
    if (lane == 31) rt = (chunk < 7) ? rp[4 * g + 4] : 0.0f;
    r[0] = lf; r[1] = v.x; r[2] = v.y; r[3] = v.z; r[4] = v.w; r[5] = rt;
}

__global__ void __launch_bounds__(256) curv_kernel(const float* __restrict__ phi,
                                                   float* __restrict__ out) {
    const int lane  = threadIdx.x;
    const int chunk = threadIdx.y;            // 0..7, warp id
    const int g     = chunk * 32 + lane;      // x-group 0..255, cols 4g..4g+3
    const float* __restrict__ p = phi + (size_t)blockIdx.z * NN * NN;

    const bool v0 = (g != 0);                 // pixel x=4g   valid?
    const bool v3 = (g != 255);               // pixel x=4g+3 valid?

    float ln = 0.0f;
    int   cnt = 0;

    for (int s = blockIdx.y; s < NSTRIPS; s += GY) {
        const int y0 = 1 + s * RSTRIP;
        const int y1 = min(y0 + RSTRIP, NN - 1);   // exclusive

        float t[6], m[6], bo[6];
        const float* rp = p + (size_t)(y0 - 1) * NN;
        load_row6(rp, g, lane, chunk, t);   rp += NN;
        load_row6(rp, g, lane, chunk, m);   rp += NN;

        for (int y = y0; y < y1; ++y) {
            load_row6(rp, g, lane, chunk, bo);  rp += NN;

            #pragma unroll
            for (int j = 0; j < 4; ++j) {
                float a   = m[j + 2] - m[j];                        // 2h * ddx
                float b   = bo[j + 1] - t[j + 1];                   // 2h * ddy
                float dxy = (bo[j + 2] - bo[j]) - (t[j + 2] - t[j]);// 4h^2 * d2dxdy
                float tt  = a - b;
                float num = dxy * tt * tt;
                float d   = fmaf(a, a, b * b);
                float sd  = sqrtf(d);
                float den = fmaf(C1 * sd, d, C2);
                float curv = __fdividef(num, den);
                float cr  = fmaf(curv, curv, -1.0f);
                cr = fmaxf(cr, 0.0f);

                float c  = m[j + 1];
                float mn = fminf(fminf(c * m[j + 2], c * m[j]),
                                 fminf(c * bo[j + 1], c * t[j + 1]));
                bool ok = (mn < 0.0f);
                if (j == 0) ok = ok && v0;
                if (j == 3) ok = ok && v3;
                if (ok) { ln += cr; cnt++; }
            }

            #pragma unroll
            for (int k = 0; k < 6; ++k) { t[k] = m[k]; m[k] = bo[k]; }
        }
    }

    // warp reduction
    #pragma unroll
    for (int o = 16; o > 0; o >>= 1) {
        ln  += __shfl_down_sync(0xffffffffu, ln, o);
        cnt += __shfl_down_sync(0xffffffffu, cnt, o);
    }

    __shared__ float sn[8];
    __shared__ int   sc[8];
    if (lane == 0) { sn[chunk] = ln; sc[chunk] = cnt; }
    __syncthreads();

    if (lane == 0 && chunk == 0) {
        double an = 0.0; long long ac = 0;
        #pragma unroll
        for (int k = 0; k < 8; ++k) { an += (double)sn[k]; ac += sc[k]; }
        atomicAdd(&g_acc[0], an);
        atomicAdd(&g_acc[1], (double)ac);
        __threadfence();
        unsigned int ticket = atomicAdd(&g_done, 1u);
        if (ticket == TOTAL_BLOCKS - 1) {
            double snum = atomicAdd(&g_acc[0], 0.0);
            double sden = atomicAdd(&g_acc[1], 0.0);
            out[0] = (float)(snum / (sden + 1e-8));
            // reset for next (graph-replayed) invocation
            atomicExch((unsigned long long*)&g_acc[0], 0ull);
            atomicExch((unsigned long long*)&g_acc[1], 0ull);
            atomicExch(&g_done, 0u);
        }
    }
}

extern "C" void kernel_launch(void* const* d_in, const int* in_sizes, int n_in,
                              void* d_out, int out_size) {
    const float* phi = (const float*)d_in[0];
    float* out = (float*)d_out;

    dim3 block(32, 8, 1);
    dim3 grid(1, GY, NB);
    curv_kernel<<<grid, block>>>(phi, out);
}

// round 6
// speedup vs baseline: 3.7707x; 1.2742x over previous
#include <cuda_runtime.h>

#define NN 1024
#define NB 32
#define NSTRIPS 128                 // 127 strips of 8 rows + 1 strip of 6 (1022 rows)
#define NUNITS (NB * NSTRIPS)       // 4096 work units
#define GRID 592                    // 148 SMs * 4 blocks
#define C1 0.122f                   // 2h
#define C2 2.2153277e-12f           // 16 h^4 * 1e-8

__device__ double g_acc[2];         // [0]=sum(zc*cr), [1]=sum(zc)
__device__ unsigned int g_done;

__device__ __forceinline__ float sqrt_approx(float x) {
    float y; asm("sqrt.approx.f32 %0, %1;" : "=f"(y) : "f"(x)); return y;
}
__device__ __forceinline__ float rcp_approx(float x) {
    float y; asm("rcp.approx.f32 %0, %1;" : "=f"(y) : "f"(x)); return y;
}

// Load 6 contiguous values (4 owned + 2 halo) for this thread's x-group.
__device__ __forceinline__ void load_row6(const float* __restrict__ rp, int x0,
                                          bool pLload, bool pLzero,
                                          bool pRload, bool pRzero,
                                          float r[6]) {
    float4 v = *reinterpret_cast<const float4*>(rp + x0);
    float lf = __shfl_up_sync(0xffffffffu, v.w, 1);
    float rt = __shfl_down_sync(0xffffffffu, v.x, 1);
    if (pLload) lf = rp[x0 - 1];
    if (pLzero) lf = 0.0f;
    if (pRload) rt = rp[x0 + 4];
    if (pRzero) rt = 0.0f;
    r[0] = lf; r[1] = v.x; r[2] = v.y; r[3] = v.z; r[4] = v.w; r[5] = rt;
}

__device__ __forceinline__ void row_compute(const float t[6], const float m[6],
                                            const float bo[6],
                                            bool v0, bool v3,
                                            float& ln, int& cnt) {
    float dv[6];
    #pragma unroll
    for (int k = 0; k < 6; ++k) dv[k] = bo[k] - t[k];          // 2h*ddy at col k
    float ph[5];
    #pragma unroll
    for (int k = 0; k < 5; ++k) ph[k] = m[k] * m[k + 1];       // horiz sign products

    #pragma unroll
    for (int j = 0; j < 4; ++j) {
        float a   = m[j + 2] - m[j];          // 2h * ddx
        float b   = dv[j + 1];                // 2h * ddy
        float dxy = dv[j + 2] - dv[j];        // 4h^2 * d2dxdy
        float tt  = a - b;
        float num = dxy * (tt * tt);          // exact factorization of reference num
        float d   = fmaf(a, a, b * b);
        float sd  = sqrt_approx(d);
        float den = fmaf(C1 * sd, d, C2);     // 2h*d^1.5 + 16h^4*eps (exact rescale)
        float curv = num * rcp_approx(den);
        float cr  = fmaf(curv, curv, -1.0f);
        cr = fmaxf(cr, 0.0f);

        float vN = m[j + 1] * t[j + 1];
        float vS = m[j + 1] * bo[j + 1];
        float mn = fminf(fminf(ph[j], ph[j + 1]), fminf(vN, vS));
        bool ok = (mn < 0.0f);
        if (j == 0) ok = ok && v0;
        if (j == 3) ok = ok && v3;
        if (ok) { ln += cr; cnt++; }
    }
}

template <int R>
__device__ __forceinline__ void do_strip(const float* __restrict__ rp, int x0,
                                         bool pLload, bool pLzero,
                                         bool pRload, bool pRzero,
                                         bool v0, bool v3,
                                         float& ln, int& cnt) {
    float buf[3][6];
    load_row6(rp, x0, pLload, pLzero, pRload, pRzero, buf[0]); rp += NN;
    load_row6(rp, x0, pLload, pLzero, pRload, pRzero, buf[1]); rp += NN;
    #pragma unroll
    for (int r = 0; r < R; ++r) {
        float* t  = buf[r % 3];
        float* m  = buf[(r + 1) % 3];
        float* bo = buf[(r + 2) % 3];
        load_row6(rp, x0, pLload, pLzero, pRload, pRzero, bo); rp += NN;
        row_compute(t, m, bo, v0, v3, ln, cnt);
    }
}

__global__ void __launch_bounds__(256, 4) curv_kernel(const float* __restrict__ phi,
                                                      float* __restrict__ out) {
    const int lane  = threadIdx.x;
    const int chunk = threadIdx.y;              // warp id 0..7
    const int g     = chunk * 32 + lane;        // x-group: columns 4g..4g+3
    const int x0    = 4 * g;

    const bool pLload = (lane == 0)  && (chunk > 0);
    const bool pLzero = (lane == 0)  && (chunk == 0);
    const bool pRload = (lane == 31) && (chunk < 7);
    const bool pRzero = (lane == 31) && (chunk == 7);
    const bool v0 = (g != 0);
    const bool v3 = (g != 255);

    float ln = 0.0f;
    int   cnt = 0;

    for (int u = blockIdx.x; u < NUNITS; u += GRID) {
        const int b = u >> 7;           // batch 0..31
        const int s = u & 127;          // strip 0..127
        const float* rp = phi + (size_t)b * NN * NN + (size_t)(s * 8) * NN;
        if (s < 127)
            do_strip<8>(rp, x0, pLload, pLzero, pRload, pRzero, v0, v3, ln, cnt);
        else
            do_strip<6>(rp, x0, pLload, pLzero, pRload, pRzero, v0, v3, ln, cnt);
    }

    // warp reduction
    #pragma unroll
    for (int o = 16; o > 0; o >>= 1) {
        ln  += __shfl_down_sync(0xffffffffu, ln, o);
        cnt += __shfl_down_sync(0xffffffffu, cnt, o);
    }

    __shared__ float sn[8];
    __shared__ int   sc[8];
    if (lane == 0) { sn[chunk] = ln; sc[chunk] = cnt; }
    __syncthreads();

    if (lane == 0 && chunk == 0) {
        double an = 0.0; long long ac = 0;
        #pragma unroll
        for (int k = 0; k < 8; ++k) { an += (double)sn[k]; ac += sc[k]; }
        atomicAdd(&g_acc[0], an);
        atomicAdd(&g_acc[1], (double)ac);
        __threadfence();
        unsigned int ticket = atomicAdd(&g_done, 1u);
        if (ticket == GRID - 1) {
            double snum = atomicAdd(&g_acc[0], 0.0);
            double sden = atomicAdd(&g_acc[1], 0.0);
            out[0] = (float)(snum / (sden + 1e-8));
            // reset for graph replay
            atomicExch((unsigned long long*)&g_acc[0], 0ull);
            atomicExch((unsigned long long*)&g_acc[1], 0ull);
            atomicExch(&g_done, 0u);
        }
    }
}

extern "C" void kernel_launch(void* const* d_in, const int* in_sizes, int n_in,
                              void* d_out, int out_size) {
    const float* phi = (const float*)d_in[0];
    float* out = (float*)d_out;

    dim3 block(32, 8, 1);
    dim3 grid(GRID, 1, 1);
    curv_kernel<<<grid, block>>>(phi, out);
}

// round 11
// speedup vs baseline: 3.9043x; 1.0354x over previous
#include <cuda_runtime.h>

#define NN 1024
#define NB 32
#define NSTRIPS 128                 // 127 strips of 8 rows + 1 strip of 6 (1022 rows)
#define NUNITS (NB * NSTRIPS)       // 4096 work units
#define GRID 592                    // 148 SMs * 4 blocks, one balanced wave
#define C1 0.122f                   // 2h
#define C2 2.2153277e-12f           // 16 h^4 * 1e-8

__device__ double g_acc[2];         // [0]=sum(zc*cr), [1]=sum(zc)
__device__ unsigned int g_done;

typedef unsigned long long f2;
#define NEG1P 0xBF800000BF800000ULL

__device__ __forceinline__ f2 pack2(float lo, float hi) {
    f2 r; asm("mov.b64 %0,{%1,%2};" : "=l"(r) : "f"(lo), "f"(hi)); return r;
}
__device__ __forceinline__ void unpack2(f2 v, float& lo, float& hi) {
    asm("mov.b64 {%0,%1},%2;" : "=f"(lo), "=f"(hi) : "l"(v));
}
__device__ __forceinline__ f2 mul2(f2 a, f2 b) {
    f2 r; asm("mul.rn.f32x2 %0,%1,%2;" : "=l"(r) : "l"(a), "l"(b)); return r;
}
__device__ __forceinline__ f2 fma2(f2 a, f2 b, f2 c) {
    f2 r; asm("fma.rn.f32x2 %0,%1,%2,%3;" : "=l"(r) : "l"(a), "l"(b), "l"(c)); return r;
}
__device__ __forceinline__ f2 sub2(f2 a, f2 b) {          // a - b
    return fma2(b, (f2)NEG1P, a);
}
__device__ __forceinline__ float sqrt_approx(float x) {
    float y; asm("sqrt.approx.f32 %0, %1;" : "=f"(y) : "f"(x)); return y;
}
__device__ __forceinline__ float rcp_approx(float x) {
    float y; asm("rcp.approx.f32 %0, %1;" : "=f"(y) : "f"(x)); return y;
}

// Load 6 contiguous values (4 owned + 2 halo) for this thread's x-group.
__device__ __forceinline__ void load_row6(const float* __restrict__ rp, int x0,
                                          bool pLload, bool pLzero,
                                          bool pRload, bool pRzero,
                                          float r[6]) {
    float4 v = *reinterpret_cast<const float4*>(rp + x0);
    float lf = __shfl_up_sync(0xffffffffu, v.w, 1);
    float rt = __shfl_down_sync(0xffffffffu, v.x, 1);
    if (pLload) lf = rp[x0 - 1];
    if (pLzero) lf = 0.0f;
    if (pRload) rt = rp[x0 + 4];
    if (pRzero) rt = 0.0f;
    r[0] = lf; r[1] = v.x; r[2] = v.y; r[3] = v.z; r[4] = v.w; r[5] = rt;
}

__device__ __forceinline__ void row_compute(const float t[6], const float m[6],
                                            const float bo[6],
                                            bool v0, bool v3,
                                            float& ln, int& cnt) {
    // vertical differences (2h * ddy at every column)
    float dv[6];
    #pragma unroll
    for (int k = 0; k < 6; ++k) dv[k] = bo[k] - t[k];

    // packed pairs: pixel pair A = (px0, px1), pair B = (px2, px3)
    f2 mL = pack2(m[0], m[1]);
    f2 mM = pack2(m[2], m[3]);
    f2 mR = pack2(m[4], m[5]);
    f2 dvL = pack2(dv[0], dv[1]);
    f2 dvM = pack2(dv[2], dv[3]);
    f2 dvR = pack2(dv[4], dv[5]);
    f2 bA  = pack2(dv[1], dv[2]);
    f2 bB  = pack2(dv[3], dv[4]);

    f2 aA   = sub2(mM, mL);        // 2h*ddx for px0,px1
    f2 aB   = sub2(mR, mM);
    f2 dxyA = sub2(dvM, dvL);      // 4h^2*d2dxdy
    f2 dxyB = sub2(dvR, dvM);
    f2 ttA  = sub2(aA, bA);
    f2 ttB  = sub2(aB, bB);
    f2 numA = mul2(dxyA, mul2(ttA, ttA));
    f2 numB = mul2(dxyB, mul2(ttB, ttB));
    f2 dA   = fma2(aA, aA, mul2(bA, bA));    // d = a^2 + b^2
    f2 dB   = fma2(aB, aB, mul2(bB, bB));

    float dd[4], nm[4];
    unpack2(dA, dd[0], dd[1]); unpack2(dB, dd[2], dd[3]);
    unpack2(numA, nm[0], nm[1]); unpack2(numB, nm[2], nm[3]);

    #pragma unroll
    for (int j = 0; j < 4; ++j) {
        float d    = dd[j];
        float sd   = sqrt_approx(d);
        float den  = fmaf(C1 * sd, d, C2);   // 2h*d^1.5 + 16h^4*eps (exact rescale)
        float curv = nm[j] * rcp_approx(den);
        float cr   = fmaf(curv, curv, -1.0f);
        cr = fmaxf(cr, 0.0f);

        // sign-xor zero-crossing: msb of OR of sign diffs
        int c = __float_as_int(m[j + 1]);
        int x1 = (c ^ __float_as_int(m[j + 2])) | (c ^ __float_as_int(m[j]));
        int x2 = (c ^ __float_as_int(bo[j + 1])) | (c ^ __float_as_int(t[j + 1]));
        bool ok = ((x1 | x2) < 0);
        if (j == 0) ok = ok && v0;
        if (j == 3) ok = ok && v3;
        if (ok) { ln += cr; cnt++; }
    }
}

template <int R>
__device__ __forceinline__ void do_strip(const float* __restrict__ rp, int x0,
                                         bool pLload, bool pLzero,
                                         bool pRload, bool pRzero,
                                         bool v0, bool v3,
                                         float& ln, int& cnt) {
    float buf[3][6];
    load_row6(rp, x0, pLload, pLzero, pRload, pRzero, buf[0]); rp += NN;
    load_row6(rp, x0, pLload, pLzero, pRload, pRzero, buf[1]); rp += NN;
    #pragma unroll
    for (int r = 0; r < R; ++r) {
        float* t  = buf[r % 3];
        float* m  = buf[(r + 1) % 3];
        float* bo = buf[(r + 2) % 3];
        load_row6(rp, x0, pLload, pLzero, pRload, pRzero, bo); rp += NN;
        row_compute(t, m, bo, v0, v3, ln, cnt);
    }
}

__global__ void __launch_bounds__(256, 4) curv_kernel(const float* __restrict__ phi,
                                                      float* __restrict__ out) {
    const int lane  = threadIdx.x;
    const int chunk = threadIdx.y;              // warp id 0..7
    const int g     = chunk * 32 + lane;        // x-group: columns 4g..4g+3
    const int x0    = 4 * g;

    const bool pLload = (lane == 0)  && (chunk > 0);
    const bool pLzero = (lane == 0)  && (chunk == 0);
    const bool pRload = (lane == 31) && (chunk < 7);
    const bool pRzero = (lane == 31) && (chunk == 7);
    const bool v0 = (g != 0);
    const bool v3 = (g != 255);

    float ln = 0.0f;
    int   cnt = 0;

    for (int u = blockIdx.x; u < NUNITS; u += GRID) {
        const int b = u >> 7;           // batch 0..31
        const int s = u & 127;          // strip 0..127
        const float* rp = phi + (size_t)b * NN * NN + (size_t)(s * 8) * NN;
        if (s < 127)
            do_strip<8>(rp, x0, pLload, pLzero, pRload, pRzero, v0, v3, ln, cnt);
        else
            do_strip<6>(rp, x0, pLload, pLzero, pRload, pRzero, v0, v3, ln, cnt);
    }

    // warp reduction
    #pragma unroll
    for (int o = 16; o > 0; o >>= 1) {
        ln  += __shfl_down_sync(0xffffffffu, ln, o);
        cnt += __shfl_down_sync(0xffffffffu, cnt, o);
    }

    __shared__ float sn[8];
    __shared__ int   sc[8];
    if (lane == 0) { sn[chunk] = ln; sc[chunk] = cnt; }
    __syncthreads();

    if (lane == 0 && chunk == 0) {
        double an = 0.0; long long ac = 0;
        #pragma unroll
        for (int k = 0; k < 8; ++k) { an += (double)sn[k]; ac += sc[k]; }
        atomicAdd(&g_acc[0], an);
        atomicAdd(&g_acc[1], (double)ac);
        __threadfence();
        unsigned int ticket = atomicAdd(&g_done, 1u);
        if (ticket == GRID - 1) {
            double snum = atomicAdd(&g_acc[0], 0.0);
            double sden = atomicAdd(&g_acc[1], 0.0);
            out[0] = (float)(snum / (sden + 1e-8));
            // reset for graph replay
            atomicExch((unsigned long long*)&g_acc[0], 0ull);
            atomicExch((unsigned long long*)&g_acc[1], 0ull);
            atomicExch(&g_done, 0u);
        }
    }
}

extern "C" void kernel_launch(void* const* d_in, const int* in_sizes, int n_in,
                              void* d_out, int out_size) {
    const float* phi = (const float*)d_in[0];
    float* out = (float*)d_out;

    dim3 block(32, 8, 1);
    dim3 grid(GRID, 1, 1);
    curv_kernel<<<grid, block>>>(phi, out);
}

// round 12
// speedup vs baseline: 4.7413x; 1.2144x over previous
#include <cuda_runtime.h>

#define NN 1024
#define NB 32
#define NSTRIPS 128                 // 127 strips of 8 rows + 1 strip of 6 (1022 rows)
#define NUNITS (NB * NSTRIPS)       // 4096 work units
#define GRID 592                    // 148 SMs * 4 blocks, one balanced residency
#define C1 0.122f                   // 2h
#define C2 2.2153277e-12f           // 16 h^4 * 1e-8

__device__ double g_acc[2];         // [0]=sum(zc*cr), [1]=sum(zc)
__device__ unsigned int g_done;

__device__ __forceinline__ float sqrt_approx(float x) {
    float y; asm("sqrt.approx.f32 %0, %1;" : "=f"(y) : "f"(x)); return y;
}
__device__ __forceinline__ float rcp_approx(float x) {
    float y; asm("rcp.approx.f32 %0, %1;" : "=f"(y) : "f"(x)); return y;
}

// Load 6 values: clamped left halo, aligned float4, clamped right halo.
// Clamped halos only ever feed boundary-masked pixels, so garbage is safe.
__device__ __forceinline__ void load_row6(const float* __restrict__ rb, int x0,
                                          int cLF, int cRT, float r[6]) {
    float4 v = *reinterpret_cast<const float4*>(rb + x0);
    r[0] = rb[cLF];
    r[1] = v.x; r[2] = v.y; r[3] = v.z; r[4] = v.w;
    r[5] = rb[cRT];
}

__device__ __forceinline__ void row_compute(const float t[6], const float m[6],
                                            const float bo[6],
                                            bool v0, bool v3,
                                            float& ln, int& cnt) {
    float dv[6];
    #pragma unroll
    for (int k = 0; k < 6; ++k) dv[k] = bo[k] - t[k];      // 2h*ddy per column

    #pragma unroll
    for (int j = 0; j < 4; ++j) {
        float a    = m[j + 2] - m[j];                      // 2h * ddx
        float b    = dv[j + 1];                            // 2h * ddy
        float dxy  = dv[j + 2] - dv[j];                    // 4h^2 * d2dxdy
        float tt   = a - b;
        float num  = dxy * (tt * tt);                      // exact factorization
        float d    = fmaf(a, a, b * b);
        float sd   = sqrt_approx(d);
        float den  = fmaf(C1 * sd, d, C2);                 // 2h*d^1.5 + 16h^4*eps
        float curv = num * rcp_approx(den);
        float cr   = fmaf(curv, curv, -1.0f);
        cr = fmaxf(cr, 0.0f);

        // sign-xor zero-crossing: msb of OR of sign differences
        int c  = __float_as_int(m[j + 1]);
        int x1 = (c ^ __float_as_int(m[j + 2])) | (c ^ __float_as_int(m[j]));
        int x2 = (c ^ __float_as_int(bo[j + 1])) | (c ^ __float_as_int(t[j + 1]));
        bool ok = ((x1 | x2) < 0);
        if (j == 0) ok = ok && v0;
        if (j == 3) ok = ok && v3;
        if (ok) { ln += cr; cnt++; }
    }
}

template <int R>
__device__ __forceinline__ void do_strip(const float* __restrict__ rb, int x0,
                                         int cLF, int cRT,
                                         bool v0, bool v3,
                                         float& ln, int& cnt) {
    float buf[3][6];
    load_row6(rb,          x0, cLF, cRT, buf[0]);
    load_row6(rb + NN,     x0, cLF, cRT, buf[1]);
    #pragma unroll
    for (int r = 0; r < R; ++r) {
        float* t  = buf[r % 3];
        float* m  = buf[(r + 1) % 3];
        float* bo = buf[(r + 2) % 3];
        load_row6(rb + (r + 2) * NN, x0, cLF, cRT, bo);    // imm offsets at unroll
        row_compute(t, m, bo, v0, v3, ln, cnt);
    }
}

__global__ void __launch_bounds__(256, 4) curv_kernel(const float* __restrict__ phi,
                                                      float* __restrict__ out) {
    const int lane  = threadIdx.x;
    const int chunk = threadIdx.y;              // warp id 0..7
    const int g     = chunk * 32 + lane;        // x-group: columns 4g..4g+3
    const int x0    = 4 * g;

    const int  cLF = (g == 0)   ? 0    : x0 - 1;   // clamped halo indices
    const int  cRT = (g == 255) ? 1023 : x0 + 4;
    const bool v0  = (g != 0);
    const bool v3  = (g != 255);

    float ln = 0.0f;
    int   cnt = 0;

    for (int u = blockIdx.x; u < NUNITS; u += GRID) {
        const int b = u >> 7;           // batch 0..31
        const int s = u & 127;          // strip 0..127
        const float* rb = phi + (size_t)b * NN * NN + (size_t)(s * 8) * NN;
        if (s < 127)
            do_strip<8>(rb, x0, cLF, cRT, v0, v3, ln, cnt);
        else
            do_strip<6>(rb, x0, cLF, cRT, v0, v3, ln, cnt);
    }

    // warp reduction
    #pragma unroll
    for (int o = 16; o > 0; o >>= 1) {
        ln  += __shfl_down_sync(0xffffffffu, ln, o);
        cnt += __shfl_down_sync(0xffffffffu, cnt, o);
    }

    __shared__ float sn[8];
    __shared__ int   sc[8];
    if (lane == 0) { sn[chunk] = ln; sc[chunk] = cnt; }
    __syncthreads();

    if (lane == 0 && chunk == 0) {
        double an = 0.0; long long ac = 0;
        #pragma unroll
        for (int k = 0; k < 8; ++k) { an += (double)sn[k]; ac += sc[k]; }
        atomicAdd(&g_acc[0], an);
        atomicAdd(&g_acc[1], (double)ac);
        __threadfence();
        unsigned int ticket = atomicAdd(&g_done, 1u);
        if (ticket == GRID - 1) {
            double snum = atomicAdd(&g_acc[0], 0.0);
            double sden = atomicAdd(&g_acc[1], 0.0);
            out[0] = (float)(snum / (sden + 1e-8));
            // reset for graph replay
            atomicExch((unsigned long long*)&g_acc[0], 0ull);
            atomicExch((unsigned long long*)&g_acc[1], 0ull);
            atomicExch(&g_done, 0u);
        }
    }
}

extern "C" void kernel_launch(void* const* d_in, const int* in_sizes, int n_in,
                              void* d_out, int out_size) {
    const float* phi = (const float*)d_in[0];
    float* out = (float*)d_out;

    dim3 block(32, 8, 1);
    dim3 grid(GRID, 1, 1);
    curv_kernel<<<grid, block>>>(phi, out);
}

// round 13
// speedup vs baseline: 4.7831x; 1.0088x over previous
#include <cuda_runtime.h>

#define NN 1024
#define NB 32
#define NSTRIPS 128                 // 127 strips of 8 rows + 1 strip of 6 (1022 rows)
#define NUNITS (NB * NSTRIPS)       // 4096 work units
#define GRID 592                    // 148 SMs * 4 blocks, one balanced residency
#define C1 0.122f                   // 2h
#define C2 2.2153277e-12f           // 16 h^4 * 1e-8

__device__ double g_acc[2];         // [0]=sum(zc*cr), [1]=sum(zc)
__device__ unsigned int g_done;

typedef unsigned long long f2;
#define NEG1P 0xBF800000BF800000ULL
#define C1P   0x3DF9DB233DF9DB23ULL   // (0.122f, 0.122f)

__device__ __forceinline__ f2 pack2(float lo, float hi) {
    f2 r; asm("mov.b64 %0,{%1,%2};" : "=l"(r) : "f"(lo), "f"(hi)); return r;
}
__device__ __forceinline__ void unpack2(f2 v, float& lo, float& hi) {
    asm("mov.b64 {%0,%1},%2;" : "=f"(lo), "=f"(hi) : "l"(v));
}
__device__ __forceinline__ f2 mul2(f2 a, f2 b) {
    f2 r; asm("mul.rn.f32x2 %0,%1,%2;" : "=l"(r) : "l"(a), "l"(b)); return r;
}
__device__ __forceinline__ f2 fma2(f2 a, f2 b, f2 c) {
    f2 r; asm("fma.rn.f32x2 %0,%1,%2,%3;" : "=l"(r) : "l"(a), "l"(b), "l"(c)); return r;
}
__device__ __forceinline__ f2 sub2(f2 a, f2 b) {          // a - b
    return fma2(b, (f2)NEG1P, a);
}
__device__ __forceinline__ float sqrt_approx(float x) {
    float y; asm("sqrt.approx.f32 %0, %1;" : "=f"(y) : "f"(x)); return y;
}
__device__ __forceinline__ float rcp_approx(float x) {
    float y; asm("rcp.approx.f32 %0, %1;" : "=f"(y) : "f"(x)); return y;
}

struct Row { float lf; float4 v; float rt; };

// Load 6 values: clamped left halo, aligned float4, clamped right halo.
// Clamped halos only feed boundary-masked pixels, so garbage there is safe.
__device__ __forceinline__ void load_row(const float* __restrict__ rb, int x0,
                                         int cLF, int cRT, Row& r) {
    r.v  = *reinterpret_cast<const float4*>(rb + x0);
    r.lf = rb[cLF];
    r.rt = rb[cRT];
}

// Scalar epilogue for one pixel: curvature-relu + sign-xor zero-crossing.
__device__ __forceinline__ void px_tail(float num, float d, float c1d,
                                        float c, float e, float w,
                                        float n, float s, bool valid,
                                        float& ln, float& lc) {
    float sd   = sqrt_approx(d);
    float den  = fmaf(sd, c1d, C2);          // 2h*d^1.5 + 16h^4*eps (exact rescale)
    float curv = num * rcp_approx(den);
    float cr   = fmaf(curv, curv, -1.0f);
    cr = fmaxf(cr, 0.0f);

    int ci = __float_as_int(c);
    int x1 = (ci ^ __float_as_int(e)) | (ci ^ __float_as_int(w));
    int x2 = (ci ^ __float_as_int(s)) | (ci ^ __float_as_int(n));
    bool ok = ((x1 | x2) < 0) && valid;
    if (ok) { ln += cr; lc += 1.0f; }
}

__device__ __forceinline__ void row_compute(const Row& t, const Row& m,
                                            const Row& bo,
                                            bool v0, bool v3,
                                            float& ln, float& lc) {
    // vertical differences: owned columns packed (native float4 pair alignment)
    f2 dvP0 = sub2(pack2(bo.v.x, bo.v.y), pack2(t.v.x, t.v.y));  // dv@X0,X1
    f2 dvP1 = sub2(pack2(bo.v.z, bo.v.w), pack2(t.v.z, t.v.w));  // dv@X2,X3
    float dvL = bo.lf - t.lf;
    float dvR = bo.rt - t.rt;
    float dv0, dv1, dv2, dv3;
    unpack2(dvP0, dv0, dv1);
    unpack2(dvP1, dv2, dv3);

    // middle pixel pair (centers X1, X2): shift-by-2 quantities stay pair-aligned
    f2 aM   = sub2(pack2(m.v.z, m.v.w), pack2(m.v.x, m.v.y)); // (X2-X0, X3-X1)
    f2 dxyM = sub2(dvP1, dvP0);                               // (dv2-dv0, dv3-dv1)
    f2 bM   = pack2(dv1, dv2);                                // only constructed pair
    f2 ttM  = sub2(aM, bM);
    f2 numM = mul2(dxyM, mul2(ttM, ttM));
    f2 dM   = fma2(aM, aM, mul2(bM, bM));
    f2 c1dM = mul2(dM, (f2)C1P);

    float d1, d2, n1, n2, cd1, cd2;
    unpack2(dM, d1, d2);
    unpack2(numM, n1, n2);
    unpack2(c1dM, cd1, cd2);

    // edge pixels (centers X0, X3): scalar
    float a0   = m.v.y - m.lf;
    float a3   = m.rt  - m.v.z;
    float dxy0 = dv1 - dvL;
    float dxy3 = dvR - dv2;
    float tt0  = a0 - dv0;
    float tt3  = a3 - dv3;
    float n0   = dxy0 * (tt0 * tt0);
    float n3   = dxy3 * (tt3 * tt3);
    float d0   = fmaf(a0, a0, dv0 * dv0);
    float d3   = fmaf(a3, a3, dv3 * dv3);
    float cd0  = C1 * d0;
    float cd3  = C1 * d3;

    px_tail(n0, d0, cd0, m.v.x, m.v.y, m.lf,  t.v.x, bo.v.x, v0,   ln, lc);
    px_tail(n1, d1, cd1, m.v.y, m.v.z, m.v.x, t.v.y, bo.v.y, true, ln, lc);
    px_tail(n2, d2, cd2, m.v.z, m.v.w, m.v.y, t.v.z, bo.v.z, true, ln, lc);
    px_tail(n3, d3, cd3, m.v.w, m.rt,  m.v.z, t.v.w, bo.v.w, v3,   ln, lc);
}

template <int R>
__device__ __forceinline__ void do_strip(const float* __restrict__ rb, int x0,
                                         int cLF, int cRT,
                                         bool v0, bool v3,
                                         float& ln, float& lc) {
    Row buf[3];
    load_row(rb,      x0, cLF, cRT, buf[0]);
    load_row(rb + NN, x0, cLF, cRT, buf[1]);
    #pragma unroll
    for (int r = 0; r < R; ++r) {
        load_row(rb + (r + 2) * NN, x0, cLF, cRT, buf[(r + 2) % 3]);
        row_compute(buf[r % 3], buf[(r + 1) % 3], buf[(r + 2) % 3],
                    v0, v3, ln, lc);
    }
}

__global__ void __launch_bounds__(256, 4) curv_kernel(const float* __restrict__ phi,
                                                      float* __restrict__ out) {
    const int lane  = threadIdx.x;
    const int chunk = threadIdx.y;              // warp id 0..7
    const int g     = chunk * 32 + lane;        // x-group: columns 4g..4g+3
    const int x0    = 4 * g;

    const int  cLF = (g == 0)   ? 0    : x0 - 1;   // clamped halo indices
    const int  cRT = (g == 255) ? 1023 : x0 + 4;
    const bool v0  = (g != 0);
    const bool v3  = (g != 255);

    float ln = 0.0f;
    float lc = 0.0f;                            // count as float (fma pipe, exact)

    for (int u = blockIdx.x; u < NUNITS; u += GRID) {
        const int b = u >> 7;           // batch 0..31
        const int s = u & 127;          // strip 0..127
        const float* rb = phi + (size_t)b * NN * NN + (size_t)(s * 8) * NN;
        if (s < 127)
            do_strip<8>(rb, x0, cLF, cRT, v0, v3, ln, lc);
        else
            do_strip<6>(rb, x0, cLF, cRT, v0, v3, ln, lc);
    }

    // warp reduction
    #pragma unroll
    for (int o = 16; o > 0; o >>= 1) {
        ln += __shfl_down_sync(0xffffffffu, ln, o);
        lc += __shfl_down_sync(0xffffffffu, lc, o);
    }

    __shared__ float sn[8];
    __shared__ float sc[8];
    if (lane == 0) { sn[chunk] = ln; sc[chunk] = lc; }
    __syncthreads();

    if (lane == 0 && chunk == 0) {
        double an = 0.0, ac = 0.0;
        #pragma unroll
        for (int k = 0; k < 8; ++k) { an += (double)sn[k]; ac += (double)sc[k]; }
        atomicAdd(&g_acc[0], an);
        atomicAdd(&g_acc[1], ac);
        __threadfence();
        unsigned int ticket = atomicAdd(&g_done, 1u);
        if (ticket == GRID - 1) {
            double snum = atomicAdd(&g_acc[0], 0.0);
            double sden = atomicAdd(&g_acc[1], 0.0);
            out[0] = (float)(snum / (sden + 1e-8));
            // reset for graph replay
            atomicExch((unsigned long long*)&g_acc[0], 0ull);
            atomicExch((unsigned long long*)&g_acc[1], 0ull);
            atomicExch(&g_done, 0u);
        }
    }
}

extern "C" void kernel_launch(void* const* d_in, const int* in_sizes, int n_in,
                              void* d_out, int out_size) {
    const float* phi = (const float*)d_in[0];
    float* out = (float*)d_out;

    dim3 block(32, 8, 1);
    dim3 grid(GRID, 1, 1);
    curv_kernel<<<grid, block>>>(phi, out);
}